// round 1
// baseline (speedup 1.0000x reference)
#include <cuda_runtime.h>
#include <math.h>

// Problem constants (fixed by the reference)
#define NS   256
#define NT   16384
#define HCH  64
#define EPS2 (1e-8f * 1e-8f)

// LUT config: piecewise-linear table of the 2-output Pade network as a
// function of x = log(d / reference_length).  x range for this data is
// ~[-4.3, 2.1]; we cover [-14, 3] with huge margin and clamp outside.
#define LUT_N    8192
#define LUT_X0   (-14.0f)
#define LUT_X1   (3.0f)
#define LUT_STEP ((LUT_X1 - LUT_X0) / (float)LUT_N)

__device__ float2 g_lut[LUT_N + 1];
__device__ float  g_c2;   // (-log(ref_len) - LUT_X0) / LUT_STEP   (runtime)

// ---------------------------------------------------------------------------
// Kernel 1: build the LUT exactly (one thread per node, 64-channel Pade net).
// ---------------------------------------------------------------------------
__global__ void build_lut_kernel(const float* __restrict__ ref,
                                 const float* __restrict__ W1,
                                 const float* __restrict__ b1,
                                 const float* __restrict__ pa,   // (H,3)
                                 const float* __restrict__ pb,   // (H,2)
                                 const float* __restrict__ W2,   // (H,2)
                                 const float* __restrict__ b2)   // (2,)
{
    int i = blockIdx.x * blockDim.x + threadIdx.x;
    if (i == 0) {
        g_c2 = (-logf(ref[0]) - LUT_X0) / LUT_STEP;
    }
    if (i > LUT_N) return;

    float xv = LUT_X0 + (float)i * LUT_STEP;   // feature value at node i
    float f0 = b2[0];
    float f1 = b2[1];
    #pragma unroll 8
    for (int h = 0; h < HCH; h++) {
        float x   = fmaf(xv, W1[h], b1[h]);
        float num = fmaf(x, fmaf(x, pa[3 * h + 2], pa[3 * h + 1]), pa[3 * h + 0]);
        float t   = x * fmaf(x, pb[2 * h + 1], pb[2 * h + 0]);
        float den = 1.0f + fabsf(t);
        float r   = num / den;
        f0 = fmaf(r, W2[2 * h + 0], f0);
        f1 = fmaf(r, W2[2 * h + 1], f1);
    }
    g_lut[i] = make_float2(f0, f1);
}

// ---------------------------------------------------------------------------
// Kernel 2: main pair loop.  One thread per target; sources + LUT in shared.
// Per pair: LG2 + RSQ (MUFU), ~24 FMA/ALU, 1 broadcast LDS.128 + 2 LDS.64.
// ---------------------------------------------------------------------------
#define TPB  128
#define GRID (NT / TPB)   // 128

__global__ __launch_bounds__(TPB)
void field_kernel(const float* __restrict__ sp,    // (NS,3)
                  const float* __restrict__ tp,    // (NT,3)
                  const float* __restrict__ str,   // (NS,)
                  float* __restrict__ out)         // (NT,4)
{
    extern __shared__ char smem[];
    float4* s_src = (float4*)smem;                              // NS * 16 B
    float2* s_lut = (float2*)(smem + NS * sizeof(float4));      // (LUT_N+1)*8 B

    int tid = threadIdx.x;

    for (int i = tid; i < NS; i += TPB)
        s_src[i] = make_float4(sp[3 * i + 0], sp[3 * i + 1], sp[3 * i + 2], str[i]);
    for (int i = tid; i <= LUT_N; i += TPB)
        s_lut[i] = g_lut[i];
    __syncthreads();

    int t = blockIdx.x * TPB + tid;     // grid covers NT exactly
    float tx = tp[3 * t + 0];
    float ty = tp[3 * t + 1];
    float tz = tp[3 * t + 2];

    // u = lg2(dsq) * C1 + c2  maps dsq directly to LUT coordinate:
    //   x = 0.5*ln(dsq) - ln(ref);  u = (x - X0)/STEP
    const float c1 = 0.5f * 0.693147180559945f / LUT_STEP;
    const float c2 = g_c2;

    float phi = 0.0f, vx = 0.0f, vy = 0.0f, vz = 0.0f;

    #pragma unroll 4
    for (int s = 0; s < NS; s++) {
        float4 S  = s_src[s];                       // broadcast
        float rx  = tx - S.x;
        float ry  = ty - S.y;
        float rz  = tz - S.z;
        float dsq = fmaf(rx, rx, fmaf(ry, ry, fmaf(rz, rz, EPS2)));
        float rin = rsqrtf(dsq);                    // MUFU.RSQ
        float u   = fmaf(__log2f(dsq), c1, c2);     // MUFU.LG2 + FMA
        u = fminf(fmaxf(u, 0.0f), (float)LUT_N - 0.5f);
        float fi  = floorf(u);
        int   idx = (int)fi;
        float fr  = u - fi;
        float2 A  = s_lut[idx];
        float2 B  = s_lut[idx + 1];
        float o0  = fmaf(fr, B.x - A.x, A.x);
        float o1  = fmaf(fr, B.y - A.y, A.y);
        phi = fmaf(o0, S.w, phi);
        float cc = o1 * S.w * rin;
        vx = fmaf(cc, rx, vx);
        vy = fmaf(cc, ry, vy);
        vz = fmaf(cc, rz, vz);
    }

    ((float4*)out)[t] = make_float4(phi, vx, vy, vz);
}

// ---------------------------------------------------------------------------
// Launch: build LUT, then evaluate field.  Both on the capture stream.
// ---------------------------------------------------------------------------
extern "C" void kernel_launch(void* const* d_in, const int* in_sizes, int n_in,
                              void* d_out, int out_size)
{
    const float* ref = (const float*)d_in[0];
    const float* sp  = (const float*)d_in[1];
    const float* tp  = (const float*)d_in[2];
    const float* str = (const float*)d_in[3];
    const float* W1  = (const float*)d_in[4];
    const float* b1  = (const float*)d_in[5];
    const float* pa  = (const float*)d_in[6];
    const float* pb  = (const float*)d_in[7];
    const float* W2  = (const float*)d_in[8];
    const float* b2  = (const float*)d_in[9];

    build_lut_kernel<<<(LUT_N + 1 + 127) / 128, 128>>>(ref, W1, b1, pa, pb, W2, b2);

    size_t smem = NS * sizeof(float4) + (LUT_N + 1) * sizeof(float2);
    cudaFuncSetAttribute(field_kernel,
                         cudaFuncAttributeMaxDynamicSharedMemorySize, (int)smem);
    field_kernel<<<GRID, TPB, smem>>>(sp, tp, str, (float*)d_out);
}

// round 2
// speedup vs baseline: 2.0423x; 2.0423x over previous
#include <cuda_runtime.h>
#include <math.h>

// Problem constants (fixed by the reference)
#define NS   256
#define NT   16384
#define HCH  64
#define EPS2 (1e-16f)

// ---------------------------------------------------------------------------
// Float-bit-indexed LUT of the 2-output Pade network as a function of dsq.
// Node i corresponds to dsq bits = DSQ_LO_BITS + (i << 16)  (7 mantissa bits
// per octave).  Range: dsq in [2^-26, 2^7)  ->  33 octaves * 128 = 4224
// segments, 4225 nodes.  x = 0.5*ln(dsq) - ln(ref); x-step ~= 2.7e-3.
// ---------------------------------------------------------------------------
#define DSQ_LO_BITS 0x32800000   // 2^-26
#define DSQ_HI_BITS 0x42FFFFFF   // just under 2^7
#define LUT_SEGS    4224
#define LUT_NODES   (LUT_SEGS + 1)

__device__ float2 g_nodes[LUT_NODES];

// ---------------------------------------------------------------------------
// Kernel 1: build node values exactly.  One WARP per node: 2 channels per
// lane + shfl reduction.  4225 warps -> good parallelism.
// ---------------------------------------------------------------------------
__global__ void build_nodes_kernel(const float* __restrict__ ref,
                                   const float* __restrict__ W1,
                                   const float* __restrict__ b1,
                                   const float* __restrict__ pa,   // (H,3)
                                   const float* __restrict__ pb,   // (H,2)
                                   const float* __restrict__ W2,   // (H,2)
                                   const float* __restrict__ b2)   // (2,)
{
    int gw   = (blockIdx.x * blockDim.x + threadIdx.x) >> 5;
    int lane = threadIdx.x & 31;
    if (gw >= LUT_NODES) return;

    int   bits = DSQ_LO_BITS + (gw << 16);
    float dsq  = __int_as_float(bits);
    float xv   = 0.5f * logf(dsq) - logf(ref[0]);   // feature at this node

    float f0 = 0.0f, f1 = 0.0f;
    #pragma unroll
    for (int k = 0; k < 2; k++) {
        int   h   = lane + 32 * k;
        float x   = fmaf(xv, W1[h], b1[h]);
        float num = fmaf(x, fmaf(x, pa[3 * h + 2], pa[3 * h + 1]), pa[3 * h + 0]);
        float t   = x * fmaf(x, pb[2 * h + 1], pb[2 * h + 0]);
        float r   = num / (1.0f + fabsf(t));
        f0 = fmaf(r, W2[2 * h + 0], f0);
        f1 = fmaf(r, W2[2 * h + 1], f1);
    }
    #pragma unroll
    for (int off = 16; off > 0; off >>= 1) {
        f0 += __shfl_xor_sync(0xffffffffu, f0, off);
        f1 += __shfl_xor_sync(0xffffffffu, f1, off);
    }
    if (lane == 0)
        g_nodes[gw] = make_float2(f0 + b2[0], f1 + b2[1]);
}

// ---------------------------------------------------------------------------
// Kernel 2: main pair loop.
// CTA = 64 targets x 8 source-teams (512 threads), grid = 256 CTAs,
// 2 CTAs/SM resident -> single wave, ~28 warps/SM.
// Per pair: 1 broadcast LDS.128 (src), 1 random LDS.128 (lut), 1 MUFU.RSQ,
// ~20 FMA/ALU.  LUT index derived straight from dsq float bits (no log).
// ---------------------------------------------------------------------------
#define TPB     512
#define TGT     64                    // targets per CTA
#define TEAMS   8                     // source teams per target
#define SRC_PER (NS / TEAMS)          // 32 sources per team
#define GRID    (NT / TGT)            // 256 CTAs

__global__ __launch_bounds__(TPB)
void field_kernel(const float* __restrict__ sp,    // (NS,3)
                  const float* __restrict__ tp,    // (NT,3)
                  const float* __restrict__ str,   // (NS,)
                  float* __restrict__ out)         // (NT,4)
{
    extern __shared__ float4 smem[];
    float4* s_lut  = smem;                       // LUT_SEGS entries
    float4* s_src  = smem + LUT_SEGS;            // NS entries
    float4* s_part = smem + LUT_SEGS + NS;       // TEAMS*TGT entries

    int tid = threadIdx.x;

    // Fill LUT: (f0_i, f1_i, (f0_{i+1}-f0_i)*2^-16, (f1_{i+1}-f1_i)*2^-16)
    for (int i = tid; i < LUT_SEGS; i += TPB) {
        float2 a = g_nodes[i];
        float2 b = g_nodes[i + 1];
        s_lut[i] = make_float4(a.x, a.y,
                               (b.x - a.x) * 0x1p-16f,
                               (b.y - a.y) * 0x1p-16f);
    }
    for (int i = tid; i < NS; i += TPB)
        s_src[i] = make_float4(sp[3 * i + 0], sp[3 * i + 1], sp[3 * i + 2], str[i]);
    __syncthreads();

    int tgt  = tid & (TGT - 1);
    int team = tid >> 6;
    int t    = blockIdx.x * TGT + tgt;

    float tx = tp[3 * t + 0];
    float ty = tp[3 * t + 1];
    float tz = tp[3 * t + 2];

    float phi = 0.0f, vx = 0.0f, vy = 0.0f, vz = 0.0f;

    int s0 = team * SRC_PER;
    #pragma unroll 4
    for (int k = 0; k < SRC_PER; k++) {
        float4 S  = s_src[s0 + k];                 // broadcast within warp
        float rx  = tx - S.x;
        float ry  = ty - S.y;
        float rz  = tz - S.z;
        float dsq = fmaf(rx, rx, fmaf(ry, ry, fmaf(rz, rz, EPS2)));
        float rin = rsqrtf(dsq);                   // MUFU.RSQ

        int bits = __float_as_int(dsq);            // positive -> int order ok
        bits = min(bits, DSQ_HI_BITS);
        bits = max(bits, DSQ_LO_BITS);
        int   idx = (bits - DSQ_LO_BITS) >> 16;
        float fr  = (float)(bits & 0xFFFF);        // low mantissa bits

        float4 L  = s_lut[idx];
        float o0  = fmaf(fr, L.z, L.x);
        float o1  = fmaf(fr, L.w, L.y);

        phi = fmaf(o0, S.w, phi);
        float cc = o1 * S.w * rin;
        vx = fmaf(cc, rx, vx);
        vy = fmaf(cc, ry, vy);
        vz = fmaf(cc, rz, vz);
    }

    s_part[team * TGT + tgt] = make_float4(phi, vx, vy, vz);
    __syncthreads();

    // Deterministic reduction: thread (tgt, comp) sums the 8 team partials.
    if (tid < TGT * 4) {
        int rt = tid >> 2;
        int rc = tid & 3;
        const float* p = (const float*)s_part;
        float acc = 0.0f;
        #pragma unroll
        for (int m = 0; m < TEAMS; m++)
            acc += p[(m * TGT + rt) * 4 + rc];
        out[(blockIdx.x * TGT + rt) * 4 + rc] = acc;
    }
}

// ---------------------------------------------------------------------------
extern "C" void kernel_launch(void* const* d_in, const int* in_sizes, int n_in,
                              void* d_out, int out_size)
{
    const float* ref = (const float*)d_in[0];
    const float* sp  = (const float*)d_in[1];
    const float* tp  = (const float*)d_in[2];
    const float* str = (const float*)d_in[3];
    const float* W1  = (const float*)d_in[4];
    const float* b1  = (const float*)d_in[5];
    const float* pa  = (const float*)d_in[6];
    const float* pb  = (const float*)d_in[7];
    const float* W2  = (const float*)d_in[8];
    const float* b2  = (const float*)d_in[9];

    // 4225 node-warps, 8 warps per CTA
    build_nodes_kernel<<<(LUT_NODES * 32 + 255) / 256, 256>>>(ref, W1, b1, pa, pb, W2, b2);

    size_t smem = (LUT_SEGS + NS + TEAMS * TGT) * sizeof(float4);
    cudaFuncSetAttribute(field_kernel,
                         cudaFuncAttributeMaxDynamicSharedMemorySize, (int)smem);
    field_kernel<<<GRID, TPB, smem>>>(sp, tp, str, (float*)d_out);
}

// round 3
// speedup vs baseline: 2.0766x; 1.0168x over previous
#include <cuda_runtime.h>
#include <math.h>

// Problem constants (fixed by the reference)
#define NS   256
#define NT   16384
#define HCH  64
#define EPS2 (1e-16f)

// ---------------------------------------------------------------------------
// Float-bit-indexed LUT over dsq, 64 segments per octave (6 mantissa bits).
// Node i: dsq bits = LO + (i<<17).  Range dsq in [2^-26, 2^8): 34 octaves
// * 64 = 2176 segments.  Channel 0 tabulates out0(x); channel 1 tabulates
// out1(x)/d (radial 1/d folded in -> no rsqrt in the hot loop).
// ---------------------------------------------------------------------------
#define DSQ_LO_BITS 0x32800000   // 2^-26
#define DSQ_HI_BITS 0x437FFFFF   // just under 2^8 = 256
#define LUT_SEGS    2176
#define LUT_NODES   (LUT_SEGS + 1)

__device__ float2 g_nodes[LUT_NODES];

// ---------------------------------------------------------------------------
// Kernel 1: build node values exactly.  One WARP per node (2 ch/lane + shfl).
// ---------------------------------------------------------------------------
__global__ void build_nodes_kernel(const float* __restrict__ ref,
                                   const float* __restrict__ W1,
                                   const float* __restrict__ b1,
                                   const float* __restrict__ pa,   // (H,3)
                                   const float* __restrict__ pb,   // (H,2)
                                   const float* __restrict__ W2,   // (H,2)
                                   const float* __restrict__ b2)   // (2,)
{
    int gw   = (blockIdx.x * blockDim.x + threadIdx.x) >> 5;
    int lane = threadIdx.x & 31;
    if (gw >= LUT_NODES) return;

    float dsq = __int_as_float(DSQ_LO_BITS + (gw << 17));
    float xv  = 0.5f * logf(dsq) - logf(ref[0]);     // feature at this node

    float f0 = 0.0f, f1 = 0.0f;
    #pragma unroll
    for (int k = 0; k < 2; k++) {
        int   h   = lane + 32 * k;
        float x   = fmaf(xv, W1[h], b1[h]);
        float num = fmaf(x, fmaf(x, pa[3 * h + 2], pa[3 * h + 1]), pa[3 * h + 0]);
        float t   = x * fmaf(x, pb[2 * h + 1], pb[2 * h + 0]);
        float r   = num / (1.0f + fabsf(t));
        f0 = fmaf(r, W2[2 * h + 0], f0);
        f1 = fmaf(r, W2[2 * h + 1], f1);
    }
    #pragma unroll
    for (int off = 16; off > 0; off >>= 1) {
        f0 += __shfl_xor_sync(0xffffffffu, f0, off);
        f1 += __shfl_xor_sync(0xffffffffu, f1, off);
    }
    if (lane == 0)
        g_nodes[gw] = make_float2(f0 + b2[0],
                                  (f1 + b2[1]) / sqrtf(dsq));   // fold 1/d
}

// ---------------------------------------------------------------------------
// Kernel 2: main pair loop.
// CTA = 32 targets x 16 source-teams (512 thr), GRID = 512, 4 CTAs/SM.
// Per pair: broadcast LDS.128 (src) + random LDS.128 (lut) + ~17 FMA/ALU,
// no MUFU.  LUT coordinate straight from dsq float bits; frac via LOP3
// exponent-splice (f = 131072 + fr/64), slopes pre-scaled accordingly.
// ---------------------------------------------------------------------------
#define TPB     512
#define TGT     32                    // targets per CTA
#define TEAMS   16                    // source teams per target
#define SRC_PER (NS / TEAMS)          // 16 sources per team
#define GRID    (NT / TGT)            // 512 CTAs

__global__ __launch_bounds__(TPB, 4)
void field_kernel(const float* __restrict__ sp,    // (NS,3)
                  const float* __restrict__ tp,    // (NT,3)
                  const float* __restrict__ str,   // (NS,)
                  float* __restrict__ out)         // (NT,4)
{
    extern __shared__ float4 smem[];
    float4* s_lut  = smem;                       // LUT_SEGS entries
    float4* s_src  = smem + LUT_SEGS;            // NS entries
    float4* s_part = smem + LUT_SEGS + NS;       // TEAMS*TGT entries

    int tid = threadIdx.x;

    // Fill LUT: (base0', base1', s0', s1') with
    //   s' = (next-cur) * 2^-11,  base' = cur - 131072 * s'
    for (int i = tid; i < LUT_SEGS; i += TPB) {
        float2 a = g_nodes[i];
        float2 b = g_nodes[i + 1];
        float s0 = (b.x - a.x) * 0x1p-11f;
        float s1 = (b.y - a.y) * 0x1p-11f;
        s_lut[i] = make_float4(fmaf(-131072.0f, s0, a.x),
                               fmaf(-131072.0f, s1, a.y), s0, s1);
    }
    for (int i = tid; i < NS; i += TPB)
        s_src[i] = make_float4(sp[3 * i + 0], sp[3 * i + 1], sp[3 * i + 2], str[i]);
    __syncthreads();

    int tgt  = tid & (TGT - 1);
    int team = tid / TGT;
    int t    = blockIdx.x * TGT + tgt;

    float tx = tp[3 * t + 0];
    float ty = tp[3 * t + 1];
    float tz = tp[3 * t + 2];

    float phi = 0.0f, vx = 0.0f, vy = 0.0f, vz = 0.0f;

    int s0i = team * SRC_PER;
    #pragma unroll 8
    for (int k = 0; k < SRC_PER; k++) {
        float4 S  = s_src[s0i + k];                // broadcast within warp
        float rx  = tx - S.x;
        float ry  = ty - S.y;
        float rz  = tz - S.z;
        float dsq = fmaf(rx, rx, fmaf(ry, ry, fmaf(rz, rz, EPS2)));

        int bits = __float_as_int(dsq);            // positive -> int order ok
        bits = min(bits, DSQ_HI_BITS);
        bits = max(bits, DSQ_LO_BITS);
        int   idx   = (bits - DSQ_LO_BITS) >> 17;
        float f     = __int_as_float((bits & 0x1FFFF) | 0x48000000);

        float4 L  = s_lut[idx];
        float o0  = fmaf(f, L.z, L.x);             // out0
        float g1  = fmaf(f, L.w, L.y);             // out1 / d

        phi = fmaf(o0, S.w, phi);
        float cc = g1 * S.w;
        vx = fmaf(cc, rx, vx);
        vy = fmaf(cc, ry, vy);
        vz = fmaf(cc, rz, vz);
    }

    s_part[team * TGT + tgt] = make_float4(phi, vx, vy, vz);
    __syncthreads();

    // Deterministic reduction: thread (tgt, comp) sums the 16 team partials.
    if (tid < TGT * 4) {
        int rt = tid >> 2;
        int rc = tid & 3;
        const float* p = (const float*)s_part;
        float acc = 0.0f;
        #pragma unroll
        for (int m = 0; m < TEAMS; m++)
            acc += p[(m * TGT + rt) * 4 + rc];
        out[(blockIdx.x * TGT + rt) * 4 + rc] = acc;
    }
}

// ---------------------------------------------------------------------------
extern "C" void kernel_launch(void* const* d_in, const int* in_sizes, int n_in,
                              void* d_out, int out_size)
{
    const float* ref = (const float*)d_in[0];
    const float* sp  = (const float*)d_in[1];
    const float* tp  = (const float*)d_in[2];
    const float* str = (const float*)d_in[3];
    const float* W1  = (const float*)d_in[4];
    const float* b1  = (const float*)d_in[5];
    const float* pa  = (const float*)d_in[6];
    const float* pb  = (const float*)d_in[7];
    const float* W2  = (const float*)d_in[8];
    const float* b2  = (const float*)d_in[9];

    build_nodes_kernel<<<(LUT_NODES * 32 + 255) / 256, 256>>>(ref, W1, b1, pa, pb, W2, b2);

    size_t smem = (LUT_SEGS + NS + TEAMS * TGT) * sizeof(float4);
    cudaFuncSetAttribute(field_kernel,
                         cudaFuncAttributeMaxDynamicSharedMemorySize, (int)smem);
    field_kernel<<<GRID, TPB, smem>>>(sp, tp, str, (float*)d_out);
}